// round 17
// baseline (speedup 1.0000x reference)
#include <cuda_runtime.h>
#include <cuda_fp16.h>
#include <math.h>
#include <stdint.h>

// ---------------- constants ----------------
#define NWAY 5
#define BB 4
#define QQ 75
#define CC 640
#define HW 121
#define SS 25
#define MS 605
#define COLS 3025
#define COLSP 3072
#define MP 128
#define BQ 300
#define NCHUNK 24       // 128-col chunks per bq
#define CHW 128
#define NSTG 10         // 640 / 64
#define NEG_INF (-3.4e38f)

// dynamic smem: 3-stage ring x (A 16K | B 16K) = 96 KB; epilogue reuses it
#define STG_BYTES 32768
#define OFF_A 0
#define OFF_B 16384
#define SM_TOTAL 98304
#define SEG_BASE 36864

// ---------------- device scratch (zero-init; pads stay 0) ----------------
__device__ __align__(256) __half g_qh[(size_t)BQ * MP * CC];     // fp16 normalized query
__device__ __align__(256) __half g_sh[(size_t)BB * COLSP * CC];  // fp16 normalized support
__device__ __align__(256) float  g_qf[(size_t)BQ * MP * CC];     // fp32 for refine
__device__ __align__(256) float  g_sf[(size_t)BB * COLSP * CC];
__device__ float g_pmax[BQ * NCHUNK * MP];
__device__ int   g_parg[BQ * NCHUNK * MP];
__device__ float g_pmax2[BQ * NCHUNK * MP];
__device__ int   g_parg2[BQ * NCHUNK * MP];
__device__ float g_ptop[BQ * NCHUNK * 6 * MP];   // [unit][clsA(3)+clsB(3)][row]
__device__ float g_logits[BQ * NWAY];

// ---------------- helpers ----------------
__device__ __forceinline__ uint32_t smem_u32(const void* p) {
    uint32_t a;
    asm("{ .reg .u64 t; cvta.to.shared.u64 t, %1; cvt.u32.u64 %0, t; }" : "=r"(a) : "l"(p));
    return a;
}
__device__ __forceinline__ void cpa(uint32_t dst, const void* src) {
    asm volatile("cp.async.cg.shared.global [%0], [%1], 16;"
                 :: "r"(dst), "l"(__cvta_generic_to_global(src)));
}
#define CP_COMMIT() asm volatile("cp.async.commit_group;" ::: "memory")
#define CP_WAIT1() asm volatile("cp.async.wait_group 1;" ::: "memory")

__device__ __forceinline__ void ldmx4(uint32_t* r, uint32_t addr) {
    asm volatile("ldmatrix.sync.aligned.m8n8.x4.shared.b16 {%0,%1,%2,%3}, [%4];"
                 : "=r"(r[0]), "=r"(r[1]), "=r"(r[2]), "=r"(r[3]) : "r"(addr));
}
__device__ __forceinline__ void mma16816(float* c, const uint32_t* a, const uint32_t* b) {
    asm volatile("mma.sync.aligned.m16n8k16.row.col.f32.f16.f16.f32 "
                 "{%0,%1,%2,%3}, {%4,%5,%6,%7}, {%8,%9}, {%0,%1,%2,%3};"
                 : "+f"(c[0]), "+f"(c[1]), "+f"(c[2]), "+f"(c[3])
                 : "r"(a[0]), "r"(a[1]), "r"(a[2]), "r"(a[3]), "r"(b[0]), "r"(b[1]));
}
__device__ __forceinline__ uint32_t swz128(uint32_t off) { return off ^ ((off >> 3) & 0x70); }

__device__ __forceinline__ void top3_ins(float& a0, float& a1, float& a2, float v) {
    if (v > a0)      { a2 = a1; a1 = a0; a0 = v; }
    else if (v > a1) { a2 = a1; a1 = v; }
    else if (v > a2) { a2 = v; }
}
// top-2 (value, col) with exact lowest-col tie-break (order-independent)
__device__ __forceinline__ void top2_ins(float& m1, int& i1, float& m2, int& i2,
                                         float v, int c) {
    if (v > m1 || (v == m1 && c < i1)) { m2 = m1; i2 = i1; m1 = v; i1 = c; }
    else if (v > m2 || (v == m2 && c < i2)) { m2 = v; i2 = c; }
}

// ---------------- dummy kernel (profiler slot alignment) ----------------
__global__ void k_nop() {}

// ---------------- k_norm: fp32 -> fp16 + fp32, [row][k] ----------------
__global__ void __launch_bounds__(128) k_norm(const float* __restrict__ qx,
                                              const float* __restrict__ sx) {
    __shared__ float inv_s[HW];
    __shared__ float tbuf[32 * HW];
    int blk = blockIdx.x, t = threadIdx.x;
    const float* in;
    __half* oh; float* of;
    if (blk < BQ) {
        in = qx + (size_t)blk * CC * HW;
        oh = g_qh + (size_t)blk * MP * CC;
        of = g_qf + (size_t)blk * MP * CC;
    } else {
        int bs = blk - BQ;
        int b = bs / SS, s = bs % SS;
        int row0 = (s / 5) * MS + (s % 5) * HW;    // class-major support row
        in = sx + (size_t)bs * CC * HW;
        oh = g_sh + ((size_t)b * COLSP + row0) * CC;
        of = g_sf + ((size_t)b * COLSP + row0) * CC;
    }
    if (t < HW) {
        float ss = 0.f;
#pragma unroll 8
        for (int c = 0; c < CC; c++) { float v = in[c * HW + t]; ss += v * v; }
        inv_s[t] = 1.0f / (sqrtf(ss) + 1e-8f);
    }
    __syncthreads();
    for (int c0 = 0; c0 < CC; c0 += 32) {
        for (int idx = t; idx < 32 * HW; idx += 128) {
            int cl = idx / HW, hw = idx - cl * HW;
            tbuf[idx] = in[(c0 + cl) * HW + hw] * inv_s[hw];
        }
        __syncthreads();
        for (int idx = t; idx < HW * 32; idx += 128) {
            int m = idx >> 5, cl = idx & 31;
            float v = tbuf[cl * HW + m];
            oh[(size_t)m * CC + c0 + cl] = __float2half(v);
            of[(size_t)m * CC + c0 + cl] = v;
        }
        __syncthreads();
    }
}

// ---------------- k_main: fp16 mma.sync GEMM, 3-stage ring ----------------
extern __shared__ __align__(1024) char dsm[];

__global__ void __launch_bounds__(512, 2) k_main() {
    uint32_t sb = smem_u32(dsm);
    int tid = threadIdx.x;
    int lane = tid & 31, w = tid >> 5;
    int warp_m = w & 3, warp_n = w >> 2;
    int m0 = warp_m * 32, n0 = warp_n * 32;

    int unit = blockIdx.x;
    int bq = unit / NCHUNK, chunk = unit % NCHUNK;
    int bi = bq / QQ;

    // ---- loop-invariant cp.async addressing (row+64 adds 8192: bit 13, carry-free
    //      since dstA < 8192 and swizzle window is bits 4-6)
    int lrow = tid >> 3, lc = (tid & 7) * 16;
    uint32_t dstA = swz128((uint32_t)lrow * 128 + lc);      // chunk 0; chunk 1 = +8192
    const char* srcA0 = (const char*)(g_qh + (size_t)bq * MP * CC) + (size_t)lrow * 1280 + lc;
    const char* srcB0 = (const char*)(g_sh + ((size_t)bi * COLSP + chunk * CHW) * CC)
                        + (size_t)lrow * 1280 + lc;

    // ---- loop-invariant ldmatrix addressing.
    //      x = row*128 + kb has bits 5-6 == 0 (kb in {0,16}), so
    //      swz128(x + kh*32) == swz128(x) ^ (kh*32)  -- XOR, NOT add (add can
    //      carry out of the swizzled bits into the row field; that was the
    //      R13 OOB crash).
    int a_row = (lane & 15), a_kb = (lane >> 4) * 16;
    int b_row = ((lane >> 4) << 3) + (lane & 7), b_kb = ((lane >> 3) & 1) * 16;
    uint32_t swA0 = swz128((uint32_t)(m0 + a_row) * 128 + a_kb);
    uint32_t swA1 = swz128((uint32_t)(m0 + 16 + a_row) * 128 + a_kb);
    uint32_t swB0 = swz128((uint32_t)(n0 + b_row) * 128 + b_kb);
    uint32_t swB1 = swz128((uint32_t)(n0 + 16 + b_row) * 128 + b_kb);

    float acc[2][4][4];
#pragma unroll
    for (int i = 0; i < 2; i++)
#pragma unroll
        for (int j = 0; j < 4; j++)
#pragma unroll
            for (int k = 0; k < 4; k++) acc[i][j][k] = 0.f;

#define LOAD_STAGE(J) do { \
    uint32_t _b = sb + ((J) % 3) * STG_BYTES; \
    int _ko = (J) * 128; \
    cpa(_b + OFF_A + dstA, srcA0 + _ko); \
    cpa(_b + OFF_A + dstA + 8192, srcA0 + 64 * 1280 + _ko); \
    cpa(_b + OFF_B + dstA, srcB0 + _ko); \
    cpa(_b + OFF_B + dstA + 8192, srcB0 + 64 * 1280 + _ko); \
    CP_COMMIT(); \
} while (0)

    LOAD_STAGE(0);
    LOAD_STAGE(1);

    for (int j = 0; j < NSTG; j++) {
        CP_WAIT1();            // stage j resident (j+1 may still fly)
        __syncthreads();       // publish stage j; all threads done reading stage j-1
        if (j + 2 < NSTG) LOAD_STAGE(j + 2);
        else CP_COMMIT();      // keep group count aligned for CP_WAIT1
        uint32_t baseA = sb + (j % 3) * STG_BYTES + OFF_A;
        uint32_t baseB = sb + (j % 3) * STG_BYTES + OFF_B;
#pragma unroll
        for (int kh = 0; kh < 4; kh++) {
            uint32_t ko = kh * 32;
            uint32_t ah[2][4], bh0[4], bh1[4];
            ldmx4(ah[0], baseA + (swA0 ^ ko));
            ldmx4(ah[1], baseA + (swA1 ^ ko));
            ldmx4(bh0, baseB + (swB0 ^ ko));
            ldmx4(bh1, baseB + (swB1 ^ ko));
#pragma unroll
            for (int mt = 0; mt < 2; mt++) {
                mma16816(acc[mt][0], ah[mt], &bh0[0]);
                mma16816(acc[mt][1], ah[mt], &bh0[2]);
                mma16816(acc[mt][2], ah[mt], &bh1[0]);
                mma16816(acc[mt][3], ah[mt], &bh1[2]);
            }
        }
    }

    // ---------------- epilogue: stage accums -> smem, parallel scan ----------
    float* Csh = (float*)dsm;      // 64 rows x stride 133 floats
    float* s_m1 = (float*)(dsm + SEG_BASE);          // [256] each
    float* s_m2 = s_m1 + 256;
    float* s_a0 = s_m1 + 512;  float* s_a1 = s_m1 + 768;  float* s_a2 = s_m1 + 1024;
    float* s_b0 = s_m1 + 1280; float* s_b1 = s_m1 + 1536; float* s_b2 = s_m1 + 1792;
    int*   s_i1 = (int*)(s_m1 + 2048);
    int*   s_i2 = (int*)(s_m1 + 2304);

    int g = lane >> 2, tq = lane & 3;
    int col0 = chunk * CHW;
    int clsA = col0 / MS;
    int bnd = (clsA + 1) * MS;

#pragma unroll
    for (int h = 0; h < 2; h++) {
        __syncthreads();
        if ((warp_m >> 1) == h) {
            int lrb = warp_m * 32 - h * 64;
#pragma unroll
            for (int mt = 0; mt < 2; mt++) {
                int lr = lrb + mt * 16 + g;
#pragma unroll
                for (int nt8 = 0; nt8 < 4; nt8++) {
                    int cl = n0 + nt8 * 8 + 2 * tq;
                    Csh[lr * 133 + cl] = acc[mt][nt8][0];
                    Csh[lr * 133 + cl + 1] = acc[mt][nt8][1];
                    Csh[(lr + 8) * 133 + cl] = acc[mt][nt8][2];
                    Csh[(lr + 8) * 133 + cl + 1] = acc[mt][nt8][3];
                }
            }
        }
        __syncthreads();
        // segment scan: 256 threads, 4 interleaved segments per row (bank-spread)
        if (tid < 256) {
            int row_l = tid >> 2, seg = tid & 3;
            int rg = h * 64 + row_l;
            if (rg < HW) {
                float m1 = NEG_INF, m2 = NEG_INF;
                int i1 = 1 << 30, i2 = 1 << 30;
                float a0 = NEG_INF, a1 = NEG_INF, a2 = NEG_INF;
                float b0 = NEG_INF, b1 = NEG_INF, b2 = NEG_INF;
                const float* row = &Csh[row_l * 133];
                if (chunk != NCHUNK - 1) {
#pragma unroll 8
                    for (int i = 0; i < 32; i++) {
                        int cl = seg + 4 * i;
                        float v = row[cl];
                        int col = col0 + cl;
                        top2_ins(m1, i1, m2, i2, v, col);
                        if (col < bnd) top3_ins(a0, a1, a2, v);
                        else           top3_ins(b0, b1, b2, v);
                    }
                } else {
#pragma unroll 8
                    for (int i = 0; i < 32; i++) {
                        int cl = seg + 4 * i;
                        int col = col0 + cl;
                        if (col < COLS) {
                            float v = row[cl];
                            top2_ins(m1, i1, m2, i2, v, col);
                            if (col < bnd) top3_ins(a0, a1, a2, v);
                            else           top3_ins(b0, b1, b2, v);
                        }
                    }
                }
                s_m1[tid] = m1; s_m2[tid] = m2;
                s_i1[tid] = i1; s_i2[tid] = i2;
                s_a0[tid] = a0; s_a1[tid] = a1; s_a2[tid] = a2;
                s_b0[tid] = b0; s_b1[tid] = b1; s_b2[tid] = b2;
            }
        }
        __syncthreads();
        // merge 4 segments per row (tie-break by col keeps exactness)
        if (tid < 64) {
            int rg = h * 64 + tid;
            if (rg < HW) {
                float M1 = NEG_INF, M2 = NEG_INF;
                int I1 = 1 << 30, I2 = 1 << 30;
                float A0 = NEG_INF, A1 = NEG_INF, A2 = NEG_INF;
                float B0 = NEG_INF, B1 = NEG_INF, B2 = NEG_INF;
#pragma unroll
                for (int seg = 0; seg < 4; seg++) {
                    int idx = tid * 4 + seg;
                    top2_ins(M1, I1, M2, I2, s_m1[idx], s_i1[idx]);
                    top2_ins(M1, I1, M2, I2, s_m2[idx], s_i2[idx]);
                    top3_ins(A0, A1, A2, s_a0[idx]);
                    top3_ins(A0, A1, A2, s_a1[idx]);
                    top3_ins(A0, A1, A2, s_a2[idx]);
                    top3_ins(B0, B1, B2, s_b0[idx]);
                    top3_ins(B0, B1, B2, s_b1[idx]);
                    top3_ins(B0, B1, B2, s_b2[idx]);
                }
                g_pmax[unit * MP + rg] = M1;
                g_parg[unit * MP + rg] = I1;
                g_pmax2[unit * MP + rg] = M2;
                g_parg2[unit * MP + rg] = I2;
                float* pt = &g_ptop[(size_t)unit * 6 * MP + rg];
                pt[0 * MP] = A0; pt[1 * MP] = A1; pt[2 * MP] = A2;
                pt[3 * MP] = B0; pt[4 * MP] = B1; pt[5 * MP] = B2;
            }
        }
    }
#undef LOAD_STAGE
}

// ---------------- k_merge: candidates -> exact refine -> MNN mask -> logits ----
__global__ void __launch_bounds__(256) k_merge() {
    int bq = blockIdx.x, m = threadIdx.x;
    int bi = bq / QQ;
    __shared__ float s_val[MP];
    __shared__ int   s_arg[MP];
    __shared__ float s_topv[NWAY * MP];
    __shared__ float s_red[256];
    __shared__ int   s_cand[HW * 8];
    __shared__ float s_exact[HW * 8];

    // ---- phase 1: merge chunk partials; build approx top-8 candidate cols ----
    if (m < HW) {
        float cv[8]; int ci[8];
#pragma unroll
        for (int j = 0; j < 8; j++) { cv[j] = NEG_INF; ci[j] = 0; }
        float ta[NWAY], tb[NWAY], tc[NWAY];
#pragma unroll
        for (int n = 0; n < NWAY; n++) { ta[n] = tb[n] = tc[n] = NEG_INF; }

#pragma unroll
        for (int ch = 0; ch < NCHUNK; ch++) {
            int u = bq * NCHUNK + ch;
            float v1 = g_pmax[u * MP + m];  int c1 = g_parg[u * MP + m];
            float v2 = g_pmax2[u * MP + m]; int c2 = g_parg2[u * MP + m];
#pragma unroll
            for (int j = 0; j < 8; j++)
                if (v1 > cv[j]) { float tv = cv[j]; cv[j] = v1; v1 = tv;
                                  int tcx = ci[j]; ci[j] = c1; c1 = tcx; }
#pragma unroll
            for (int j = 0; j < 8; j++)
                if (v2 > cv[j]) { float tv = cv[j]; cv[j] = v2; v2 = tv;
                                  int tcx = ci[j]; ci[j] = c2; c2 = tcx; }
            const int clsA = (ch * CHW) / MS;
            const float* pt = &g_ptop[(size_t)u * 6 * MP + m];
#pragma unroll
            for (int k = 0; k < 3; k++)
                top3_ins(ta[clsA], tb[clsA], tc[clsA], pt[k * MP]);
            if (clsA + 1 < NWAY) {
#pragma unroll
                for (int k = 0; k < 3; k++)
                    top3_ins(ta[clsA + 1], tb[clsA + 1], tc[clsA + 1], pt[(3 + k) * MP]);
            }
        }
#pragma unroll
        for (int j = 0; j < 8; j++) s_cand[m * 8 + j] = ci[j];
#pragma unroll
        for (int n = 0; n < NWAY; n++)
            s_topv[n * MP + m] = (ta[n] + tb[n] + tc[n]) * (1.0f / 3.0f);
    }
    __syncthreads();

    // ---- phase 2: warp-cooperative exact fp32 dots (8 warps) ----
    {
        int wd = m >> 5, lane = m & 31;
        for (int r = wd; r < HW; r += 8) {
            const float4* A4 = (const float4*)(g_qf + ((size_t)bq * MP + r) * CC);
            const float4* B4[8];
#pragma unroll
            for (int j = 0; j < 8; j++)
                B4[j] = (const float4*)(g_sf + ((size_t)bi * COLSP + s_cand[r * 8 + j]) * CC);
            float sums[8];
#pragma unroll
            for (int j = 0; j < 8; j++) sums[j] = 0.f;
#pragma unroll
            for (int i = 0; i < 5; i++) {
                float4 a = A4[lane + 32 * i];
#pragma unroll
                for (int j = 0; j < 8; j++) {
                    float4 b = B4[j][lane + 32 * i];
                    sums[j] += a.x * b.x + a.y * b.y + a.z * b.z + a.w * b.w;
                }
            }
#pragma unroll
            for (int j = 0; j < 8; j++) {
                float v = sums[j];
#pragma unroll
                for (int o = 16; o; o >>= 1) v += __shfl_xor_sync(0xFFFFFFFFu, v, o);
                if (lane == 0) s_exact[r * 8 + j] = v;
            }
        }
    }
    __syncthreads();

    // ---- phase 3: exact argmax per row (lowest col on ties) ----
    if (m < HW) {
        float emax = NEG_INF; int earg = 1 << 30;
#pragma unroll
        for (int j = 0; j < 8; j++) {
            float v = s_exact[m * 8 + j];
            int c = s_cand[m * 8 + j];
            if (v > emax || (v == emax && c < earg)) { emax = v; earg = c; }
        }
        s_val[m] = emax + 1.0f;
        s_arg[m] = earg;
    }
    __syncthreads();

    // ---- phase 4: MNN mask + logits ----
    bool mask = false;
    if (m < HW) {
        int wbest = -1; float bv = 0.0f;
        for (int mp2 = 0; mp2 < HW; mp2++)
            if (s_arg[mp2] == s_arg[m] && s_val[mp2] > bv) { bv = s_val[mp2]; wbest = mp2; }
        mask = (wbest == m);
    }
    for (int n = 0; n < NWAY; n++) {
        s_red[m] = (m < HW && mask) ? s_topv[n * MP + m] : 0.0f;
        __syncthreads();
        for (int s = 128; s > 0; s >>= 1) {
            if (m < s) s_red[m] += s_red[m + s];
            __syncthreads();
        }
        if (m == 0) g_logits[bq * NWAY + n] = s_red[0] * 0.5f;
        __syncthreads();
    }
}

// ---------------- cross-entropy mean ----------------
__global__ void __launch_bounds__(512) k_loss(const int* __restrict__ qy, float* __restrict__ out) {
    __shared__ float sl[512];
    int t = threadIdx.x;
    float li = 0.f;
    if (t < BQ) {
        const float* l = &g_logits[t * NWAY];
        float mx = l[0];
#pragma unroll
        for (int n = 1; n < NWAY; n++) mx = fmaxf(mx, l[n]);
        float se = 0.f;
#pragma unroll
        for (int n = 0; n < NWAY; n++) se += expf(l[n] - mx);
        li = -(l[qy[t]] - mx - logf(se));
    }
    sl[t] = li;
    __syncthreads();
    for (int s = 256; s > 0; s >>= 1) {
        if (t < s) sl[t] += sl[t + s];
        __syncthreads();
    }
    if (t == 0) out[0] = sl[0] * (1.0f / BQ);
}

// ---------------- launch ----------------
extern "C" void kernel_launch(void* const* d_in, const int* in_sizes, int n_in,
                              void* d_out, int out_size) {
    const float* sup = (const float*)d_in[0];
    const float* qry = (const float*)d_in[1];
    const int* qy = (const int*)d_in[3];
    float* out = (float*)d_out;

    cudaFuncSetAttribute(k_main, cudaFuncAttributeMaxDynamicSharedMemorySize, SM_TOTAL);

    k_norm<<<BQ + BB * SS, 128>>>(qry, sup);
    k_nop<<<1, 32>>>();          // profiler slot alignment: keep k_main on the
    k_nop<<<1, 32>>>();          // ncu "-s 5 -c 1" capture slot
    k_main<<<BQ * NCHUNK, 512, SM_TOTAL>>>();
    k_merge<<<BQ, 256>>>();
    k_loss<<<1, 512>>>(qy, out);
}